// round 14
// baseline (speedup 1.0000x reference)
#include <cuda_runtime.h>
#include <stdint.h>
#include <math.h>

#define SQ       2048
#define NH       16
#define DQK      576
#define KVL      512
#define NTOP     1024
#define SCALINGF 0.08838834764831845f  // 128^-0.5

// ------------------ device scratch (no allocation) ------------------
__device__ float g_ql  [SQ * 2048];
__device__ float g_ckv [SQ * 128];
__device__ float g_wtmp[SQ * NH];
__device__ float g_iq  [SQ * NH * 128];
__device__ float g_ik  [SQ * 128];
__device__ float g_w   [SQ * NH];
__device__ float g_q   [SQ * NH * DQK];
__device__ float g_kv  [SQ * DQK];          // tf32-pre-rounded (attention only)
__device__ float g_score[SQ * SQ];
__device__ int   g_topk [SQ * NTOP];
__device__ float g_attn [SQ * NH * KVL];

// ------------------ cp.async helpers ------------------
__device__ __forceinline__ void cp16(void* dst, const void* src) {
    unsigned s = (unsigned)__cvta_generic_to_shared(dst);
    asm volatile("cp.async.cg.shared.global [%0], [%1], 16;\n" :: "r"(s), "l"(src));
}
__device__ __forceinline__ void cp_commit() {
    asm volatile("cp.async.commit_group;\n" ::: "memory");
}
__device__ __forceinline__ void cp_wait1() {
    asm volatile("cp.async.wait_group 1;\n" ::: "memory");
}

// ------------------ tf32 mma helpers ------------------
__device__ __forceinline__ uint32_t cvt_tf32(float x) {
    uint32_t r; asm("cvt.rna.tf32.f32 %0, %1;" : "=r"(r) : "f"(x)); return r;
}
__device__ __forceinline__ void mma_tf32(float* c,
    uint32_t a0, uint32_t a1, uint32_t a2, uint32_t a3,
    uint32_t b0, uint32_t b1)
{
    asm volatile(
        "mma.sync.aligned.m16n8k8.row.col.f32.tf32.tf32.f32 "
        "{%0,%1,%2,%3}, {%4,%5,%6,%7}, {%8,%9}, {%0,%1,%2,%3};\n"
        : "+f"(c[0]), "+f"(c[1]), "+f"(c[2]), "+f"(c[3])
        : "r"(a0), "r"(a1), "r"(a2), "r"(a3), "r"(b0), "r"(b1));
}

// ------------------ fast exact-fp32 SGEMM: C = A @ B^T, 128x128 tiles ------------------
__global__ __launch_bounds__(256) void sgemm128_k(
    const float* __restrict__ A, const float* __restrict__ B, float* __restrict__ C,
    int M, int N, int K, int lda, int ldb, int ldc)
{
    __shared__ float As[16][132];
    __shared__ float Bs[16][132];
    int tid = threadIdx.x;
    int m0 = blockIdx.y * 128, n0 = blockIdx.x * 128;
    int row8 = (tid >> 4) << 3, col8 = (tid & 15) << 3;
    float acc[8][8] = {};

    for (int k0 = 0; k0 < K; k0 += 16) {
        #pragma unroll
        for (int u = 0; u < 2; u++) {
            int f = tid * 2 + u;
            int r = f >> 2, c = f & 3;
            float4 av = *(const float4*)&A[(long long)(m0 + r) * lda + k0 + c * 4];
            As[c * 4 + 0][r] = av.x; As[c * 4 + 1][r] = av.y;
            As[c * 4 + 2][r] = av.z; As[c * 4 + 3][r] = av.w;
            float4 bv = *(const float4*)&B[(long long)(n0 + r) * ldb + k0 + c * 4];
            Bs[c * 4 + 0][r] = bv.x; Bs[c * 4 + 1][r] = bv.y;
            Bs[c * 4 + 2][r] = bv.z; Bs[c * 4 + 3][r] = bv.w;
        }
        __syncthreads();
        #pragma unroll
        for (int kk = 0; kk < 16; kk++) {
            float a[8], b[8];
            *(float4*)&a[0] = *(float4*)&As[kk][row8];
            *(float4*)&a[4] = *(float4*)&As[kk][row8 + 4];
            *(float4*)&b[0] = *(float4*)&Bs[kk][col8];
            *(float4*)&b[4] = *(float4*)&Bs[kk][col8 + 4];
            #pragma unroll
            for (int i = 0; i < 8; i++)
                #pragma unroll
                for (int j = 0; j < 8; j++)
                    acc[i][j] = fmaf(a[i], b[j], acc[i][j]);
        }
        __syncthreads();
    }
    #pragma unroll
    for (int i = 0; i < 8; i++) {
        float4 v0 = { acc[i][0], acc[i][1], acc[i][2], acc[i][3] };
        float4 v1 = { acc[i][4], acc[i][5], acc[i][6], acc[i][7] };
        float* crow = &C[(long long)(m0 + row8 + i) * ldc + n0 + col8];
        *(float4*)&crow[0] = v0;
        *(float4*)&crow[4] = v1;
    }
}

// ------------------ dual exact-fp32 GEMM: ckv = hs@wk^T, wtmp = hs@wproj^T ------------------
__global__ __launch_bounds__(256) void dual_k(
    const float* __restrict__ hs, const float* __restrict__ wk,
    const float* __restrict__ wproj)
{
    __shared__ float As[16][65];
    __shared__ float Bs[16][65];
    int tid = threadIdx.x, tx = tid & 15, ty = tid >> 4;
    int m0 = blockIdx.y * 64, n0 = blockIdx.x * 64;
    float acc[4][4] = {};
    for (int k0 = 0; k0 < 2048; k0 += 16) {
        for (int e = tid; e < 1024; e += 256) {
            int m = e >> 4, k = e & 15;
            As[k][m] = hs[(long long)(m0 + m) * 2048 + k0 + k];
        }
        for (int e = tid; e < 1024; e += 256) {
            int n = e >> 4, k = e & 15;
            int gn = n0 + n;
            float v = 0.f;
            if (gn < 128)      v = wk[(long long)gn * 2048 + k0 + k];
            else if (gn < 144) v = wproj[(long long)(gn - 128) * 2048 + k0 + k];
            Bs[k][n] = v;
        }
        __syncthreads();
        #pragma unroll
        for (int kk = 0; kk < 16; kk++) {
            float a[4], b[4];
            #pragma unroll
            for (int i = 0; i < 4; i++) a[i] = As[kk][ty * 4 + i];
            #pragma unroll
            for (int j = 0; j < 4; j++) b[j] = Bs[kk][tx * 4 + j];
            #pragma unroll
            for (int i = 0; i < 4; i++)
                #pragma unroll
                for (int j = 0; j < 4; j++) acc[i][j] += a[i] * b[j];
        }
        __syncthreads();
    }
    #pragma unroll
    for (int i = 0; i < 4; i++) {
        int gm = m0 + ty * 4 + i;
        #pragma unroll
        for (int j = 0; j < 4; j++) {
            int gn = n0 + tx * 4 + j;
            if (gn < 128)      g_ckv[gm * 128 + gn] = acc[i][j];
            else if (gn < 144) g_wtmp[gm * 16 + gn - 128] = acc[i][j];
        }
    }
}

// ------------------ tensor-core GEMM, 3xTF32: C = A @ op(B) ------------------
__global__ __launch_bounds__(256) void tgemm_k(
    const float* __restrict__ A, const float* __restrict__ B, float* __restrict__ C,
    int M, int N, int K, int lda, int ldb, int ldc,
    long long sA, long long sB, long long sC, int transB)
{
    A += (long long)blockIdx.z * sA;
    B += (long long)blockIdx.z * sB;
    C += (long long)blockIdx.z * sC;
    __shared__ float As[64 * 33], Ae[64 * 33], Bs[64 * 33], Be[64 * 33];
    int tid = threadIdx.x, lane = tid & 31, warp = tid >> 5;
    int wm = (warp & 3) * 16, wn = (warp >> 2) * 32;
    int g = lane >> 2, tg = lane & 3;
    int m0 = blockIdx.y * 64, n0 = blockIdx.x * 64;
    float acc[4][4] = {};

    for (int k0 = 0; k0 < K; k0 += 32) {
        for (int e = tid; e < 2048; e += 256) {
            int m = e >> 5, k = e & 31;
            float v = A[(long long)(m0 + m) * lda + k0 + k];
            float t = __uint_as_float(cvt_tf32(v));
            As[m * 33 + k] = t;
            Ae[m * 33 + k] = __uint_as_float(cvt_tf32(v - t));
        }
        if (transB) {
            for (int e = tid; e < 2048; e += 256) {
                int n = e >> 5, k = e & 31;
                float v = B[(long long)(n0 + n) * ldb + k0 + k];
                float t = __uint_as_float(cvt_tf32(v));
                Bs[n * 33 + k] = t;
                Be[n * 33 + k] = __uint_as_float(cvt_tf32(v - t));
            }
        } else {
            for (int e = tid; e < 2048; e += 256) {
                int n = e & 63, k = e >> 6;
                float v = B[(long long)(k0 + k) * ldb + n0 + n];
                float t = __uint_as_float(cvt_tf32(v));
                Bs[n * 33 + k] = t;
                Be[n * 33 + k] = __uint_as_float(cvt_tf32(v - t));
            }
        }
        __syncthreads();
        #pragma unroll
        for (int kc = 0; kc < 4; kc++) {
            int kb = kc * 8;
            uint32_t a0 = __float_as_uint(As[(wm + g) * 33 + kb + tg]);
            uint32_t a1 = __float_as_uint(As[(wm + g + 8) * 33 + kb + tg]);
            uint32_t a2 = __float_as_uint(As[(wm + g) * 33 + kb + tg + 4]);
            uint32_t a3 = __float_as_uint(As[(wm + g + 8) * 33 + kb + tg + 4]);
            uint32_t r0 = __float_as_uint(Ae[(wm + g) * 33 + kb + tg]);
            uint32_t r1 = __float_as_uint(Ae[(wm + g + 8) * 33 + kb + tg]);
            uint32_t r2 = __float_as_uint(Ae[(wm + g) * 33 + kb + tg + 4]);
            uint32_t r3 = __float_as_uint(Ae[(wm + g + 8) * 33 + kb + tg + 4]);
            #pragma unroll
            for (int nc = 0; nc < 4; nc++) {
                uint32_t b0 = __float_as_uint(Bs[(wn + nc * 8 + g) * 33 + kb + tg]);
                uint32_t b1 = __float_as_uint(Bs[(wn + nc * 8 + g) * 33 + kb + tg + 4]);
                uint32_t e0 = __float_as_uint(Be[(wn + nc * 8 + g) * 33 + kb + tg]);
                uint32_t e1 = __float_as_uint(Be[(wn + nc * 8 + g) * 33 + kb + tg + 4]);
                mma_tf32(acc[nc], r0, r1, r2, r3, b0, b1);
                mma_tf32(acc[nc], a0, a1, a2, a3, e0, e1);
                mma_tf32(acc[nc], a0, a1, a2, a3, b0, b1);
            }
        }
        __syncthreads();
    }
    #pragma unroll
    for (int nc = 0; nc < 4; nc++) {
        int col = n0 + wn + nc * 8 + 2 * tg;
        float2 v0 = { acc[nc][0], acc[nc][1] };
        float2 v1 = { acc[nc][2], acc[nc][3] };
        *(float2*)&C[(long long)(m0 + wm + g) * ldc + col]     = v0;
        *(float2*)&C[(long long)(m0 + wm + g + 8) * ldc + col] = v1;
    }
}

// ------------------ prep: rope / rmsnorm / concats; kv tf32-pre-rounded ------------------
__global__ __launch_bounds__(128) void prep_k(
    const float* __restrict__ cosb, const float* __restrict__ sinb,
    const float* __restrict__ k_pass, const float* __restrict__ k_rot,
    const float* __restrict__ q_rot, const float* __restrict__ k_norm_w,
    const float* __restrict__ wproj_b)
{
    int s = blockIdx.x, t = threadIdx.x;
    const float* cs = cosb + s * 64;
    const float* sn = sinb + s * 64;
    if (t < 32) {
        float x0 = g_ckv[s * 128 + 2 * t], x1 = g_ckv[s * 128 + 2 * t + 1];
        g_ik[s * 128 + t]      = x0 * cs[t]      - x1 * sn[t];
        g_ik[s * 128 + 32 + t] = x1 * cs[32 + t] + x0 * sn[32 + t];
    }
    __shared__ float partials[4];
    float v = 0.f;
    if (t < 64) { float x = g_ckv[s * 128 + 64 + t]; v = x * x; }
    for (int o = 16; o > 0; o >>= 1) v += __shfl_xor_sync(0xffffffffu, v, o);
    if ((t & 31) == 0) partials[t >> 5] = v;
    __syncthreads();
    float var = (partials[0] + partials[1]) * (1.f / 64.f);
    float inv = rsqrtf(var + 1e-6f);
    if (t < 64)
        g_ik[s * 128 + 64 + t] = g_ckv[s * 128 + 64 + t] * inv * k_norm_w[t];
    for (int u = t; u < 16 * 32; u += 128) {
        int h = u >> 5, i = u & 31;
        float x0 = g_ql[s * 2048 + h * 128 + 2 * i];
        float x1 = g_ql[s * 2048 + h * 128 + 2 * i + 1];
        g_iq[(s * 16 + h) * 128 + i]      = x0 * cs[i]      - x1 * sn[i];
        g_iq[(s * 16 + h) * 128 + 32 + i] = x1 * cs[32 + i] + x0 * sn[32 + i];
    }
    for (int u = t; u < 16 * 64; u += 128) {
        int h = u >> 6, i = u & 63;
        g_iq[(s * 16 + h) * 128 + 64 + i] = g_ql[s * 2048 + h * 128 + 64 + i];
    }
    if (t < 16) g_w[s * 16 + t] = fabsf(g_wtmp[s * 16 + t] + wproj_b[t]);
    for (int u = t; u < 512; u += 128)
        g_kv[s * 576 + u] = __uint_as_float(cvt_tf32(k_pass[s * 512 + u]));
    if (t < 64)
        g_kv[s * 576 + 512 + t] = __uint_as_float(cvt_tf32(k_rot[s * 64 + t]));
    for (int u = t; u < 16 * 64; u += 128) {
        int h = u >> 6, j = u & 63;
        g_q[(s * 16 + h) * 576 + 512 + j] = q_rot[(h * 2048 + s) * 64 + j];
    }
}

// ------------------ indexer scores for rows q >= 1024 (fp32, exact) ------------------
__global__ __launch_bounds__(256) void score_k()
{
    __shared__ float Qs[32][65];
    __shared__ float Ks[32][65];
    __shared__ float ws[64];
    int q0 = 1024 + blockIdx.y * 64;
    int k0 = blockIdx.x * 64;
    if (k0 > q0 + 63) return;
    int tid = threadIdx.x, tx = tid & 15, ty = tid >> 4;
    float acc[4][4] = {};
    for (int h = 0; h < 16; h++) {
        float dacc[4][4] = {};
        for (int d0 = 0; d0 < 128; d0 += 32) {
            __syncthreads();
            for (int e = tid; e < 2048; e += 256) {
                int m = e >> 5, dd = e & 31;
                Qs[dd][m] = g_iq[((q0 + m) * 16 + h) * 128 + d0 + dd];
                Ks[dd][m] = g_ik[(k0 + m) * 128 + d0 + dd];
            }
            __syncthreads();
            #pragma unroll
            for (int dd = 0; dd < 32; dd++) {
                float a[4], b[4];
                #pragma unroll
                for (int i = 0; i < 4; i++) a[i] = Qs[dd][ty * 4 + i];
                #pragma unroll
                for (int j = 0; j < 4; j++) b[j] = Ks[dd][tx * 4 + j];
                #pragma unroll
                for (int i = 0; i < 4; i++)
                    #pragma unroll
                    for (int j = 0; j < 4; j++) dacc[i][j] += a[i] * b[j];
            }
        }
        __syncthreads();
        if (tid < 64) ws[tid] = g_w[(q0 + tid) * 16 + h];
        __syncthreads();
        #pragma unroll
        for (int i = 0; i < 4; i++)
            #pragma unroll
            for (int j = 0; j < 4; j++)
                acc[i][j] += ws[ty * 4 + i] * fmaxf(dacc[i][j] * SCALINGF, 0.f);
    }
    #pragma unroll
    for (int i = 0; i < 4; i++)
        #pragma unroll
        for (int j = 0; j < 4; j++)
            g_score[(q0 + ty * 4 + i) * 2048 + k0 + tx * 4 + j] = acc[i][j];
}

// ------------------ top-1024 per row (bitonic, jax tie-break) ------------------
__global__ __launch_bounds__(1024) void topk_k()
{
    __shared__ unsigned long long key[2048];
    int q = 1024 + blockIdx.x;
    int t = threadIdx.x;
    for (int u = t; u < 2048; u += 1024) {
        unsigned long long kk = 0ull;
        if (u <= q) {
            unsigned int b = __float_as_uint(g_score[q * 2048 + u]);  // score >= 0
            kk = ((unsigned long long)b << 32) | (unsigned int)(~u);
        }
        key[u] = kk;
    }
    __syncthreads();
    for (int ks = 2; ks <= 2048; ks <<= 1) {
        for (int j = ks >> 1; j > 0; j >>= 1) {
            int i = ((t & ~(j - 1)) << 1) | (t & (j - 1));
            int p = i | j;
            bool desc = (i & ks) == 0;
            unsigned long long a = key[i], b = key[p];
            if ((a < b) == desc) { key[i] = b; key[p] = a; }
            __syncthreads();
        }
    }
    g_topk[q * 1024 + t] = (int)(~(unsigned int)(key[t] & 0xFFFFFFFFull));
}

// ------------------ flash attention: 256 thr, 16-key tiles, 2 blocks/SM ------------------
#define KP   580
#define PPP  20
#define KVB16 (16 * KP)
// floats: kv 2*KVB16 + part 8*272 + p 16*PPP + f/l 32 + sel 1024
#define ATTN_SMEM ((2*KVB16 + 8*272 + 16*PPP + 32 + 1024) * 4)

__global__ __launch_bounds__(256, 2) void attn_k()
{
    extern __shared__ float sm[];
    float* kvb  = sm;                    // 2*9280
    float* part = kvb + 2 * KVB16;       // 8*272
    float* p_s  = part + 8 * 272;        // 16*20
    float* f_s  = p_s + 16 * PPP;        // 16
    float* l_s  = f_s + 16;              // 16
    int*   sel_s = (int*)(l_s + 16);     // 1024

    int q = blockIdx.x, t = threadIdx.x;
    int L = (q < 1024) ? (q + 1) : 1024;
    const int* sel = (q < 1024) ? (const int*)0 : &g_topk[q * 1024];
    int nt = (L + 15) >> 4;

    int wid = t >> 5, lane = t & 31;
    int g = lane >> 2, tg = lane & 3;
    int gj = t >> 4, gf = t & 15;        // gather: 16 rows x 16 lanes

    // tile-0 prefetch (global sel once)
    {
        float* dst = kvb + gj * KP;
        if (gj < L) {
            int keyi = sel ? sel[gj] : gj;
            const float* src = &g_kv[keyi * 576];
            #pragma unroll
            for (int i = 0; i < 9; i++) {
                int f4 = gf + 16 * i;
                cp16(dst + f4 * 4, src + f4 * 4);
            }
        } else {
            float4 z = {0, 0, 0, 0};
            #pragma unroll
            for (int i = 0; i < 9; i++)
                *(float4*)(dst + (gf + 16 * i) * 4) = z;
        }
    }
    cp_commit();

    if (sel)
        for (int i = t; i < 1024; i += 256) sel_s[i] = sel[i];

    // q fragments: warp wid owns 9 k-chunks {wid + 8*i}, dims [c*8, c*8+8)
    uint32_t qr[9][4];
    {
        const float* qrow = &g_q[q * 16 * 576];
        #pragma unroll
        for (int i = 0; i < 9; i++) {
            int kb = (wid + 8 * i) * 8;
            qr[i][0] = cvt_tf32(qrow[g * 576 + kb + tg]);
            qr[i][1] = cvt_tf32(qrow[(g + 8) * 576 + kb + tg]);
            qr[i][2] = cvt_tf32(qrow[g * 576 + kb + tg + 4]);
            qr[i][3] = cvt_tf32(qrow[(g + 8) * 576 + kb + tg + 4]);
        }
    }
    __syncthreads();   // sel_s visible

    // softmax state: half-warp per head (head = 2*wid + (lane>>4), key = lane&15)
    int sh = 2 * wid + (lane >> 4);
    int sk = lane & 15;
    float m_cur = -1e30f, l_cur = 0.f;

    // PV: warp owns 64 dims [wid*64, wid*64+64)
    float acc[8][4] = {};

    for (int tile = 0; tile < nt; tile++) {
        int buf = tile & 1;
        float* kvs = kvb + buf * KVB16;
        // prefetch next tile (indices from smem)
        if (tile + 1 < nt) {
            int jj = (tile + 1) * 16 + gj;
            float* dst = kvb + (buf ^ 1) * KVB16 + gj * KP;
            if (jj < L) {
                int keyi = sel ? sel_s[jj] : jj;
                const float* src = &g_kv[keyi * 576];
                #pragma unroll
                for (int i = 0; i < 9; i++) {
                    int f4 = gf + 16 * i;
                    cp16(dst + f4 * 4, src + f4 * 4);
                }
            } else {
                float4 z = {0, 0, 0, 0};
                #pragma unroll
                for (int i = 0; i < 9; i++)
                    *(float4*)(dst + (gf + 16 * i) * 4) = z;
            }
        }
        cp_commit();
        cp_wait1();
        __syncthreads();

        // ---- QK: warp's 9 chunks x (16 heads x 16 keys), q in regs ----
        {
            float c4[2][4] = {};
            #pragma unroll
            for (int i = 0; i < 9; i++) {
                int kb = (wid + 8 * i) * 8;
                #pragma unroll
                for (int nc2 = 0; nc2 < 2; nc2++) {
                    uint32_t b0 = __float_as_uint(kvs[(nc2 * 8 + g) * KP + kb + tg]);
                    uint32_t b1 = __float_as_uint(kvs[(nc2 * 8 + g) * KP + kb + tg + 4]);
                    mma_tf32(c4[nc2], qr[i][0], qr[i][1], qr[i][2], qr[i][3], b0, b1);
                }
            }
            float* pp = part + wid * 272;
            #pragma unroll
            for (int nc2 = 0; nc2 < 2; nc2++) {
                pp[g * 17 + nc2 * 8 + 2 * tg]           = c4[nc2][0];
                pp[g * 17 + nc2 * 8 + 2 * tg + 1]       = c4[nc2][1];
                pp[(g + 8) * 17 + nc2 * 8 + 2 * tg]     = c4[nc2][2];
                pp[(g + 8) * 17 + nc2 * 8 + 2 * tg + 1] = c4[nc2][3];
            }
        }
        __syncthreads();

        // ---- reduce 8 partials + online softmax (half-warp per head) ----
        {
            float val = 0.f;
            #pragma unroll
            for (int ws = 0; ws < 8; ws++)
                val += part[ws * 272 + sh * 17 + sk];
            val *= SCALINGF;
            int jj = tile * 16 + sk;
            val = (jj < L) ? val : -1e30f;
            float mx = val;
            #pragma unroll
            for (int o = 8; o > 0; o >>= 1)
                mx = fmaxf(mx, __shfl_xor_sync(0xffffffffu, mx, o));
            float m_new = fmaxf(m_cur, mx);
            float factor = __expf(m_cur - m_new);
            float p = __uint_as_float(cvt_tf32(__expf(val - m_new)));
            float ps = p;
            #pragma unroll
            for (int o = 8; o > 0; o >>= 1)
                ps += __shfl_xor_sync(0xffffffffu, ps, o);
            l_cur = l_cur * factor + ps;
            m_cur = m_new;
            p_s[sh * PPP + sk] = p;
            if (sk == 0) f_s[sh] = factor;
        }
        __syncthreads();

        // ---- PV: warp owns 64 dims; rescale + mma-accumulate (16 keys = 2 kc) ----
        {
            int nb = wid * 64;
            float fg = f_s[g], fg8 = f_s[g + 8];
            #pragma unroll
            for (int c2 = 0; c2 < 8; c2++) {
                acc[c2][0] *= fg;  acc[c2][1] *= fg;
                acc[c2][2] *= fg8; acc[c2][3] *= fg8;
            }
            #pragma unroll
            for (int kc = 0; kc < 2; kc++) {
                uint32_t a0 = __float_as_uint(p_s[g * PPP + kc * 8 + tg]);
                uint32_t a1 = __float_as_uint(p_s[(g + 8) * PPP + kc * 8 + tg]);
                uint32_t a2 = __float_as_uint(p_s[g * PPP + kc * 8 + tg + 4]);
                uint32_t a3 = __float_as_uint(p_s[(g + 8) * PPP + kc * 8 + tg + 4]);
                #pragma unroll
                for (int c2 = 0; c2 < 8; c2++) {
                    uint32_t b0 = __float_as_uint(kvs[(kc * 8 + tg) * KP + nb + c2 * 8 + g]);
                    uint32_t b1 = __float_as_uint(kvs[(kc * 8 + tg + 4) * KP + nb + c2 * 8 + g]);
                    mma_tf32(acc[c2], a0, a1, a2, a3, b0, b1);
                }
            }
        }
        __syncthreads();   // kvs(buf) consumed before tile+2 prefetch
    }

    if (sk == 0) l_s[sh] = l_cur;
    __syncthreads();

    {
        int nb = wid * 64;
        float ig = 1.f / l_s[g], ig8 = 1.f / l_s[g + 8];
        #pragma unroll
        for (int c2 = 0; c2 < 8; c2++) {
            int d = nb + c2 * 8 + 2 * tg;
            float2 v0 = { acc[c2][0] * ig,  acc[c2][1] * ig  };
            float2 v1 = { acc[c2][2] * ig8, acc[c2][3] * ig8 };
            *(float2*)&g_attn[(q * 16 + g) * 512 + d]       = v0;
            *(float2*)&g_attn[(q * 16 + g + 8) * 512 + d]   = v1;
        }
    }
}

// ------------------ launcher ------------------
extern "C" void kernel_launch(void* const* d_in, const int* in_sizes, int n_in,
                              void* d_out, int out_size)
{
    const float* q_latent = (const float*)d_in[0];
    const float* hs       = (const float*)d_in[1];
    const float* cosb     = (const float*)d_in[2];
    const float* sinb     = (const float*)d_in[3];
    const float* q_pass   = (const float*)d_in[4];
    const float* q_rot    = (const float*)d_in[5];
    const float* k_pass   = (const float*)d_in[6];
    const float* k_rot    = (const float*)d_in[7];
    const float* kv_b     = (const float*)d_in[9];
    const float* wq_b     = (const float*)d_in[10];
    const float* wk       = (const float*)d_in[11];
    const float* k_norm   = (const float*)d_in[12];
    const float* wproj    = (const float*)d_in[13];
    const float* wproj_b  = (const float*)d_in[14];
    float* out = (float*)d_out;

    float *ql, *qbuf, *attn;
    cudaGetSymbolAddress((void**)&ql,   g_ql);
    cudaGetSymbolAddress((void**)&qbuf, g_q);
    cudaGetSymbolAddress((void**)&attn, g_attn);

    // (1) ql = q_latent @ wq_b^T (exact fp32)
    sgemm128_k<<<dim3(16, 16), 256>>>(q_latent, wq_b, ql,
        2048, 2048, 1536, 1536, 1536, 2048);
    // (2) ckv + wtmp (exact fp32)
    dual_k<<<dim3(3, 32), 256>>>(hs, wk, wproj);
    // (3) rope / rmsnorm / concat
    prep_k<<<2048, 128>>>(cosb, sinb, k_pass, k_rot, q_rot, k_norm, wproj_b);
    // (4) indexer scores  <- ncu capture slot
    score_k<<<dim3(32, 16), 256>>>();
    // (5) q_abs (3xTF32)
    tgemm_k<<<dim3(8, 32, 16), 256>>>(q_pass, kv_b, qbuf,
        2048, 512, 128, 128, 512, 9216,
        2048LL * 128, 256LL * 512, 576, 0);
    // (6) top-1024
    topk_k<<<1024, 1024>>>();
    // (7) gathered flash attention (2 blocks/SM)
    cudaFuncSetAttribute(attn_k, cudaFuncAttributeMaxDynamicSharedMemorySize, ATTN_SMEM);
    attn_k<<<2048, 256, ATTN_SMEM>>>();
    // (8) out = attn @ v_b^T (3xTF32)
    tgemm_k<<<dim3(2, 32, 16), 256>>>(attn, kv_b + 128 * 512, out,
        2048, 128, 512, 8192, 512, 2048,
        512, 256LL * 512, 128, 1);
}

// round 15
// speedup vs baseline: 1.0110x; 1.0110x over previous
#include <cuda_runtime.h>
#include <stdint.h>
#include <math.h>

#define SQ       2048
#define NH       16
#define DQK      576
#define KVL      512
#define NTOP     1024
#define SCALINGF 0.08838834764831845f  // 128^-0.5

// ------------------ device scratch (no allocation) ------------------
__device__ float g_ql  [SQ * 2048];
__device__ float g_ckv [SQ * 128];
__device__ float g_wtmp[SQ * NH];
__device__ float g_iq  [SQ * NH * 128];
__device__ float g_ik  [SQ * 128];
__device__ float g_w   [SQ * NH];
__device__ float g_q   [SQ * NH * DQK];
__device__ float g_kv  [SQ * DQK];          // tf32-pre-rounded (attention only)
__device__ float g_score[SQ * SQ];
__device__ int   g_topk [SQ * NTOP];
__device__ float g_attn [SQ * NH * KVL];

// ------------------ cp.async helpers ------------------
__device__ __forceinline__ void cp16(void* dst, const void* src) {
    unsigned s = (unsigned)__cvta_generic_to_shared(dst);
    asm volatile("cp.async.cg.shared.global [%0], [%1], 16;\n" :: "r"(s), "l"(src));
}
__device__ __forceinline__ void cp_commit() {
    asm volatile("cp.async.commit_group;\n" ::: "memory");
}
__device__ __forceinline__ void cp_wait1() {
    asm volatile("cp.async.wait_group 1;\n" ::: "memory");
}

// ------------------ tf32 mma helpers ------------------
__device__ __forceinline__ uint32_t cvt_tf32(float x) {
    uint32_t r; asm("cvt.rna.tf32.f32 %0, %1;" : "=r"(r) : "f"(x)); return r;
}
__device__ __forceinline__ void mma_tf32(float* c,
    uint32_t a0, uint32_t a1, uint32_t a2, uint32_t a3,
    uint32_t b0, uint32_t b1)
{
    asm volatile(
        "mma.sync.aligned.m16n8k8.row.col.f32.tf32.tf32.f32 "
        "{%0,%1,%2,%3}, {%4,%5,%6,%7}, {%8,%9}, {%0,%1,%2,%3};\n"
        : "+f"(c[0]), "+f"(c[1]), "+f"(c[2]), "+f"(c[3])
        : "r"(a0), "r"(a1), "r"(a2), "r"(a3), "r"(b0), "r"(b1));
}

// ------------------ fast exact-fp32 SGEMM: C = A @ B^T, 128x128 tiles ------------------
__global__ __launch_bounds__(256) void sgemm128_k(
    const float* __restrict__ A, const float* __restrict__ B, float* __restrict__ C,
    int M, int N, int K, int lda, int ldb, int ldc)
{
    __shared__ float As[16][132];
    __shared__ float Bs[16][132];
    int tid = threadIdx.x;
    int m0 = blockIdx.y * 128, n0 = blockIdx.x * 128;
    int row8 = (tid >> 4) << 3, col8 = (tid & 15) << 3;
    float acc[8][8] = {};

    for (int k0 = 0; k0 < K; k0 += 16) {
        #pragma unroll
        for (int u = 0; u < 2; u++) {
            int f = tid * 2 + u;
            int r = f >> 2, c = f & 3;
            float4 av = *(const float4*)&A[(long long)(m0 + r) * lda + k0 + c * 4];
            As[c * 4 + 0][r] = av.x; As[c * 4 + 1][r] = av.y;
            As[c * 4 + 2][r] = av.z; As[c * 4 + 3][r] = av.w;
            float4 bv = *(const float4*)&B[(long long)(n0 + r) * ldb + k0 + c * 4];
            Bs[c * 4 + 0][r] = bv.x; Bs[c * 4 + 1][r] = bv.y;
            Bs[c * 4 + 2][r] = bv.z; Bs[c * 4 + 3][r] = bv.w;
        }
        __syncthreads();
        #pragma unroll
        for (int kk = 0; kk < 16; kk++) {
            float a[8], b[8];
            *(float4*)&a[0] = *(float4*)&As[kk][row8];
            *(float4*)&a[4] = *(float4*)&As[kk][row8 + 4];
            *(float4*)&b[0] = *(float4*)&Bs[kk][col8];
            *(float4*)&b[4] = *(float4*)&Bs[kk][col8 + 4];
            #pragma unroll
            for (int i = 0; i < 8; i++)
                #pragma unroll
                for (int j = 0; j < 8; j++)
                    acc[i][j] = fmaf(a[i], b[j], acc[i][j]);
        }
        __syncthreads();
    }
    #pragma unroll
    for (int i = 0; i < 8; i++) {
        float4 v0 = { acc[i][0], acc[i][1], acc[i][2], acc[i][3] };
        float4 v1 = { acc[i][4], acc[i][5], acc[i][6], acc[i][7] };
        float* crow = &C[(long long)(m0 + row8 + i) * ldc + n0 + col8];
        *(float4*)&crow[0] = v0;
        *(float4*)&crow[4] = v1;
    }
}

// ------------------ dual exact-fp32 GEMM: ckv = hs@wk^T, wtmp = hs@wproj^T ------------------
__global__ __launch_bounds__(256) void dual_k(
    const float* __restrict__ hs, const float* __restrict__ wk,
    const float* __restrict__ wproj)
{
    __shared__ float As[16][65];
    __shared__ float Bs[16][65];
    int tid = threadIdx.x, tx = tid & 15, ty = tid >> 4;
    int m0 = blockIdx.y * 64, n0 = blockIdx.x * 64;
    float acc[4][4] = {};
    for (int k0 = 0; k0 < 2048; k0 += 16) {
        for (int e = tid; e < 1024; e += 256) {
            int m = e >> 4, k = e & 15;
            As[k][m] = hs[(long long)(m0 + m) * 2048 + k0 + k];
        }
        for (int e = tid; e < 1024; e += 256) {
            int n = e >> 4, k = e & 15;
            int gn = n0 + n;
            float v = 0.f;
            if (gn < 128)      v = wk[(long long)gn * 2048 + k0 + k];
            else if (gn < 144) v = wproj[(long long)(gn - 128) * 2048 + k0 + k];
            Bs[k][n] = v;
        }
        __syncthreads();
        #pragma unroll
        for (int kk = 0; kk < 16; kk++) {
            float a[4], b[4];
            #pragma unroll
            for (int i = 0; i < 4; i++) a[i] = As[kk][ty * 4 + i];
            #pragma unroll
            for (int j = 0; j < 4; j++) b[j] = Bs[kk][tx * 4 + j];
            #pragma unroll
            for (int i = 0; i < 4; i++)
                #pragma unroll
                for (int j = 0; j < 4; j++) acc[i][j] += a[i] * b[j];
        }
        __syncthreads();
    }
    #pragma unroll
    for (int i = 0; i < 4; i++) {
        int gm = m0 + ty * 4 + i;
        #pragma unroll
        for (int j = 0; j < 4; j++) {
            int gn = n0 + tx * 4 + j;
            if (gn < 128)      g_ckv[gm * 128 + gn] = acc[i][j];
            else if (gn < 144) g_wtmp[gm * 16 + gn - 128] = acc[i][j];
        }
    }
}

// ------------------ tensor-core GEMM, 3xTF32: C = A @ op(B) ------------------
__global__ __launch_bounds__(256) void tgemm_k(
    const float* __restrict__ A, const float* __restrict__ B, float* __restrict__ C,
    int M, int N, int K, int lda, int ldb, int ldc,
    long long sA, long long sB, long long sC, int transB)
{
    A += (long long)blockIdx.z * sA;
    B += (long long)blockIdx.z * sB;
    C += (long long)blockIdx.z * sC;
    __shared__ float As[64 * 33], Ae[64 * 33], Bs[64 * 33], Be[64 * 33];
    int tid = threadIdx.x, lane = tid & 31, warp = tid >> 5;
    int wm = (warp & 3) * 16, wn = (warp >> 2) * 32;
    int g = lane >> 2, tg = lane & 3;
    int m0 = blockIdx.y * 64, n0 = blockIdx.x * 64;
    float acc[4][4] = {};

    for (int k0 = 0; k0 < K; k0 += 32) {
        for (int e = tid; e < 2048; e += 256) {
            int m = e >> 5, k = e & 31;
            float v = A[(long long)(m0 + m) * lda + k0 + k];
            float t = __uint_as_float(cvt_tf32(v));
            As[m * 33 + k] = t;
            Ae[m * 33 + k] = __uint_as_float(cvt_tf32(v - t));
        }
        if (transB) {
            for (int e = tid; e < 2048; e += 256) {
                int n = e >> 5, k = e & 31;
                float v = B[(long long)(n0 + n) * ldb + k0 + k];
                float t = __uint_as_float(cvt_tf32(v));
                Bs[n * 33 + k] = t;
                Be[n * 33 + k] = __uint_as_float(cvt_tf32(v - t));
            }
        } else {
            for (int e = tid; e < 2048; e += 256) {
                int n = e & 63, k = e >> 6;
                float v = B[(long long)(k0 + k) * ldb + n0 + n];
                float t = __uint_as_float(cvt_tf32(v));
                Bs[n * 33 + k] = t;
                Be[n * 33 + k] = __uint_as_float(cvt_tf32(v - t));
            }
        }
        __syncthreads();
        #pragma unroll
        for (int kc = 0; kc < 4; kc++) {
            int kb = kc * 8;
            uint32_t a0 = __float_as_uint(As[(wm + g) * 33 + kb + tg]);
            uint32_t a1 = __float_as_uint(As[(wm + g + 8) * 33 + kb + tg]);
            uint32_t a2 = __float_as_uint(As[(wm + g) * 33 + kb + tg + 4]);
            uint32_t a3 = __float_as_uint(As[(wm + g + 8) * 33 + kb + tg + 4]);
            uint32_t r0 = __float_as_uint(Ae[(wm + g) * 33 + kb + tg]);
            uint32_t r1 = __float_as_uint(Ae[(wm + g + 8) * 33 + kb + tg]);
            uint32_t r2 = __float_as_uint(Ae[(wm + g) * 33 + kb + tg + 4]);
            uint32_t r3 = __float_as_uint(Ae[(wm + g + 8) * 33 + kb + tg + 4]);
            #pragma unroll
            for (int nc = 0; nc < 4; nc++) {
                uint32_t b0 = __float_as_uint(Bs[(wn + nc * 8 + g) * 33 + kb + tg]);
                uint32_t b1 = __float_as_uint(Bs[(wn + nc * 8 + g) * 33 + kb + tg + 4]);
                uint32_t e0 = __float_as_uint(Be[(wn + nc * 8 + g) * 33 + kb + tg]);
                uint32_t e1 = __float_as_uint(Be[(wn + nc * 8 + g) * 33 + kb + tg + 4]);
                mma_tf32(acc[nc], r0, r1, r2, r3, b0, b1);
                mma_tf32(acc[nc], a0, a1, a2, a3, e0, e1);
                mma_tf32(acc[nc], a0, a1, a2, a3, b0, b1);
            }
        }
        __syncthreads();
    }
    #pragma unroll
    for (int nc = 0; nc < 4; nc++) {
        int col = n0 + wn + nc * 8 + 2 * tg;
        float2 v0 = { acc[nc][0], acc[nc][1] };
        float2 v1 = { acc[nc][2], acc[nc][3] };
        *(float2*)&C[(long long)(m0 + wm + g) * ldc + col]     = v0;
        *(float2*)&C[(long long)(m0 + wm + g + 8) * ldc + col] = v1;
    }
}

// ------------------ prep: rope / rmsnorm / concats; kv tf32-pre-rounded ------------------
__global__ __launch_bounds__(128) void prep_k(
    const float* __restrict__ cosb, const float* __restrict__ sinb,
    const float* __restrict__ k_pass, const float* __restrict__ k_rot,
    const float* __restrict__ q_rot, const float* __restrict__ k_norm_w,
    const float* __restrict__ wproj_b)
{
    int s = blockIdx.x, t = threadIdx.x;
    const float* cs = cosb + s * 64;
    const float* sn = sinb + s * 64;
    if (t < 32) {
        float x0 = g_ckv[s * 128 + 2 * t], x1 = g_ckv[s * 128 + 2 * t + 1];
        g_ik[s * 128 + t]      = x0 * cs[t]      - x1 * sn[t];
        g_ik[s * 128 + 32 + t] = x1 * cs[32 + t] + x0 * sn[32 + t];
    }
    __shared__ float partials[4];
    float v = 0.f;
    if (t < 64) { float x = g_ckv[s * 128 + 64 + t]; v = x * x; }
    for (int o = 16; o > 0; o >>= 1) v += __shfl_xor_sync(0xffffffffu, v, o);
    if ((t & 31) == 0) partials[t >> 5] = v;
    __syncthreads();
    float var = (partials[0] + partials[1]) * (1.f / 64.f);
    float inv = rsqrtf(var + 1e-6f);
    if (t < 64)
        g_ik[s * 128 + 64 + t] = g_ckv[s * 128 + 64 + t] * inv * k_norm_w[t];
    for (int u = t; u < 16 * 32; u += 128) {
        int h = u >> 5, i = u & 31;
        float x0 = g_ql[s * 2048 + h * 128 + 2 * i];
        float x1 = g_ql[s * 2048 + h * 128 + 2 * i + 1];
        g_iq[(s * 16 + h) * 128 + i]      = x0 * cs[i]      - x1 * sn[i];
        g_iq[(s * 16 + h) * 128 + 32 + i] = x1 * cs[32 + i] + x0 * sn[32 + i];
    }
    for (int u = t; u < 16 * 64; u += 128) {
        int h = u >> 6, i = u & 63;
        g_iq[(s * 16 + h) * 128 + 64 + i] = g_ql[s * 2048 + h * 128 + 64 + i];
    }
    if (t < 16) g_w[s * 16 + t] = fabsf(g_wtmp[s * 16 + t] + wproj_b[t]);
    for (int u = t; u < 512; u += 128)
        g_kv[s * 576 + u] = __uint_as_float(cvt_tf32(k_pass[s * 512 + u]));
    if (t < 64)
        g_kv[s * 576 + 512 + t] = __uint_as_float(cvt_tf32(k_rot[s * 64 + t]));
    for (int u = t; u < 16 * 64; u += 128) {
        int h = u >> 6, j = u & 63;
        g_q[(s * 16 + h) * 576 + 512 + j] = q_rot[(h * 2048 + s) * 64 + j];
    }
}

// ------------------ indexer scores, triangular grid (fp32, exact) ------------------
__global__ __launch_bounds__(256) void score_k()
{
    __shared__ float Qs[32][65];
    __shared__ float Ks[32][65];
    __shared__ float ws[64];
    // map 1D bid -> (row block i, k block) over lower triangle: row i has 17+i blocks
    int bid = blockIdx.x;
    int i = 0, c = 0;
    #pragma unroll
    for (int r = 0; r < 16; r++) {
        int n = 17 + r;
        if (bid >= c && bid < c + n) { i = r; break; }
        c += n;
    }
    int q0 = 1024 + i * 64;
    int k0 = (bid - c) * 64;
    int tid = threadIdx.x, tx = tid & 15, ty = tid >> 4;
    float acc[4][4] = {};
    for (int h = 0; h < 16; h++) {
        float dacc[4][4] = {};
        for (int d0 = 0; d0 < 128; d0 += 32) {
            __syncthreads();
            for (int e = tid; e < 2048; e += 256) {
                int m = e >> 5, dd = e & 31;
                Qs[dd][m] = g_iq[((q0 + m) * 16 + h) * 128 + d0 + dd];
                Ks[dd][m] = g_ik[(k0 + m) * 128 + d0 + dd];
            }
            __syncthreads();
            #pragma unroll
            for (int dd = 0; dd < 32; dd++) {
                float a[4], b[4];
                #pragma unroll
                for (int i2 = 0; i2 < 4; i2++) a[i2] = Qs[dd][ty * 4 + i2];
                #pragma unroll
                for (int j = 0; j < 4; j++) b[j] = Ks[dd][tx * 4 + j];
                #pragma unroll
                for (int i2 = 0; i2 < 4; i2++)
                    #pragma unroll
                    for (int j = 0; j < 4; j++) dacc[i2][j] += a[i2] * b[j];
            }
        }
        __syncthreads();
        if (tid < 64) ws[tid] = g_w[(q0 + tid) * 16 + h];
        __syncthreads();
        #pragma unroll
        for (int i2 = 0; i2 < 4; i2++)
            #pragma unroll
            for (int j = 0; j < 4; j++)
                acc[i2][j] += ws[ty * 4 + i2] * fmaxf(dacc[i2][j] * SCALINGF, 0.f);
    }
    #pragma unroll
    for (int i2 = 0; i2 < 4; i2++)
        #pragma unroll
        for (int j = 0; j < 4; j++)
            g_score[(q0 + ty * 4 + i2) * 2048 + k0 + tx * 4 + j] = acc[i2][j];
}

// ------------------ top-1024 per row (bitonic, jax tie-break) ------------------
__global__ __launch_bounds__(1024) void topk_k()
{
    __shared__ unsigned long long key[2048];
    int q = 1024 + blockIdx.x;
    int t = threadIdx.x;
    for (int u = t; u < 2048; u += 1024) {
        unsigned long long kk = 0ull;
        if (u <= q) {
            unsigned int b = __float_as_uint(g_score[q * 2048 + u]);  // score >= 0
            kk = ((unsigned long long)b << 32) | (unsigned int)(~u);
        }
        key[u] = kk;
    }
    __syncthreads();
    for (int ks = 2; ks <= 2048; ks <<= 1) {
        for (int j = ks >> 1; j > 0; j >>= 1) {
            int i = ((t & ~(j - 1)) << 1) | (t & (j - 1));
            int p = i | j;
            bool desc = (i & ks) == 0;
            unsigned long long a = key[i], b = key[p];
            if ((a < b) == desc) { key[i] = b; key[p] = a; }
            __syncthreads();
        }
    }
    g_topk[q * 1024 + t] = (int)(~(unsigned int)(key[t] & 0xFFFFFFFFull));
}

// ------------------ flash attention: 256 thr, 16-key tiles, 2 blocks/SM ------------------
#define KP   580
#define PPP  20
#define KVB16 (16 * KP)
#define ATTN_SMEM ((2*KVB16 + 8*272 + 16*PPP + 32 + 1024) * 4)

__global__ __launch_bounds__(256, 2) void attn_k()
{
    extern __shared__ float sm[];
    float* kvb  = sm;
    float* part = kvb + 2 * KVB16;
    float* p_s  = part + 8 * 272;
    float* f_s  = p_s + 16 * PPP;
    float* l_s  = f_s + 16;
    int*   sel_s = (int*)(l_s + 16);

    int q = blockIdx.x, t = threadIdx.x;
    int L = (q < 1024) ? (q + 1) : 1024;
    const int* sel = (q < 1024) ? (const int*)0 : &g_topk[q * 1024];
    int nt = (L + 15) >> 4;

    int wid = t >> 5, lane = t & 31;
    int g = lane >> 2, tg = lane & 3;
    int gj = t >> 4, gf = t & 15;

    {
        float* dst = kvb + gj * KP;
        if (gj < L) {
            int keyi = sel ? sel[gj] : gj;
            const float* src = &g_kv[keyi * 576];
            #pragma unroll
            for (int i = 0; i < 9; i++) {
                int f4 = gf + 16 * i;
                cp16(dst + f4 * 4, src + f4 * 4);
            }
        } else {
            float4 z = {0, 0, 0, 0};
            #pragma unroll
            for (int i = 0; i < 9; i++)
                *(float4*)(dst + (gf + 16 * i) * 4) = z;
        }
    }
    cp_commit();

    if (sel)
        for (int i = t; i < 1024; i += 256) sel_s[i] = sel[i];

    uint32_t qr[9][4];
    {
        const float* qrow = &g_q[q * 16 * 576];
        #pragma unroll
        for (int i = 0; i < 9; i++) {
            int kb = (wid + 8 * i) * 8;
            qr[i][0] = cvt_tf32(qrow[g * 576 + kb + tg]);
            qr[i][1] = cvt_tf32(qrow[(g + 8) * 576 + kb + tg]);
            qr[i][2] = cvt_tf32(qrow[g * 576 + kb + tg + 4]);
            qr[i][3] = cvt_tf32(qrow[(g + 8) * 576 + kb + tg + 4]);
        }
    }
    __syncthreads();

    int sh = 2 * wid + (lane >> 4);
    int sk = lane & 15;
    float m_cur = -1e30f, l_cur = 0.f;
    float acc[8][4] = {};

    for (int tile = 0; tile < nt; tile++) {
        int buf = tile & 1;
        float* kvs = kvb + buf * KVB16;
        if (tile + 1 < nt) {
            int jj = (tile + 1) * 16 + gj;
            float* dst = kvb + (buf ^ 1) * KVB16 + gj * KP;
            if (jj < L) {
                int keyi = sel ? sel_s[jj] : jj;
                const float* src = &g_kv[keyi * 576];
                #pragma unroll
                for (int i = 0; i < 9; i++) {
                    int f4 = gf + 16 * i;
                    cp16(dst + f4 * 4, src + f4 * 4);
                }
            } else {
                float4 z = {0, 0, 0, 0};
                #pragma unroll
                for (int i = 0; i < 9; i++)
                    *(float4*)(dst + (gf + 16 * i) * 4) = z;
            }
        }
        cp_commit();
        cp_wait1();
        __syncthreads();

        {
            float c4[2][4] = {};
            #pragma unroll
            for (int i = 0; i < 9; i++) {
                int kb = (wid + 8 * i) * 8;
                #pragma unroll
                for (int nc2 = 0; nc2 < 2; nc2++) {
                    uint32_t b0 = __float_as_uint(kvs[(nc2 * 8 + g) * KP + kb + tg]);
                    uint32_t b1 = __float_as_uint(kvs[(nc2 * 8 + g) * KP + kb + tg + 4]);
                    mma_tf32(c4[nc2], qr[i][0], qr[i][1], qr[i][2], qr[i][3], b0, b1);
                }
            }
            float* pp = part + wid * 272;
            #pragma unroll
            for (int nc2 = 0; nc2 < 2; nc2++) {
                pp[g * 17 + nc2 * 8 + 2 * tg]           = c4[nc2][0];
                pp[g * 17 + nc2 * 8 + 2 * tg + 1]       = c4[nc2][1];
                pp[(g + 8) * 17 + nc2 * 8 + 2 * tg]     = c4[nc2][2];
                pp[(g + 8) * 17 + nc2 * 8 + 2 * tg + 1] = c4[nc2][3];
            }
        }
        __syncthreads();

        {
            float val = 0.f;
            #pragma unroll
            for (int ws = 0; ws < 8; ws++)
                val += part[ws * 272 + sh * 17 + sk];
            val *= SCALINGF;
            int jj = tile * 16 + sk;
            val = (jj < L) ? val : -1e30f;
            float mx = val;
            #pragma unroll
            for (int o = 8; o > 0; o >>= 1)
                mx = fmaxf(mx, __shfl_xor_sync(0xffffffffu, mx, o));
            float m_new = fmaxf(m_cur, mx);
            float factor = __expf(m_cur - m_new);
            float p = __uint_as_float(cvt_tf32(__expf(val - m_new)));
            float ps = p;
            #pragma unroll
            for (int o = 8; o > 0; o >>= 1)
                ps += __shfl_xor_sync(0xffffffffu, ps, o);
            l_cur = l_cur * factor + ps;
            m_cur = m_new;
            p_s[sh * PPP + sk] = p;
            if (sk == 0) f_s[sh] = factor;
        }
        __syncthreads();

        {
            int nb = wid * 64;
            float fg = f_s[g], fg8 = f_s[g + 8];
            #pragma unroll
            for (int c2 = 0; c2 < 8; c2++) {
                acc[c2][0] *= fg;  acc[c2][1] *= fg;
                acc[c2][2] *= fg8; acc[c2][3] *= fg8;
            }
            #pragma unroll
            for (int kc = 0; kc < 2; kc++) {
                uint32_t a0 = __float_as_uint(p_s[g * PPP + kc * 8 + tg]);
                uint32_t a1 = __float_as_uint(p_s[(g + 8) * PPP + kc * 8 + tg]);
                uint32_t a2 = __float_as_uint(p_s[g * PPP + kc * 8 + tg + 4]);
                uint32_t a3 = __float_as_uint(p_s[(g + 8) * PPP + kc * 8 + tg + 4]);
                #pragma unroll
                for (int c2 = 0; c2 < 8; c2++) {
                    uint32_t b0 = __float_as_uint(kvs[(kc * 8 + tg) * KP + nb + c2 * 8 + g]);
                    uint32_t b1 = __float_as_uint(kvs[(kc * 8 + tg + 4) * KP + nb + c2 * 8 + g]);
                    mma_tf32(acc[c2], a0, a1, a2, a3, b0, b1);
                }
            }
        }
        __syncthreads();
    }

    if (sk == 0) l_s[sh] = l_cur;
    __syncthreads();

    {
        int nb = wid * 64;
        float ig = 1.f / l_s[g], ig8 = 1.f / l_s[g + 8];
        #pragma unroll
        for (int c2 = 0; c2 < 8; c2++) {
            int d = nb + c2 * 8 + 2 * tg;
            float2 v0 = { acc[c2][0] * ig,  acc[c2][1] * ig  };
            float2 v1 = { acc[c2][2] * ig8, acc[c2][3] * ig8 };
            *(float2*)&g_attn[(q * 16 + g) * 512 + d]       = v0;
            *(float2*)&g_attn[(q * 16 + g + 8) * 512 + d]   = v1;
        }
    }
}

// ------------------ launcher: fork-join streams for DAG overlap ------------------
extern "C" void kernel_launch(void* const* d_in, const int* in_sizes, int n_in,
                              void* d_out, int out_size)
{
    const float* q_latent = (const float*)d_in[0];
    const float* hs       = (const float*)d_in[1];
    const float* cosb     = (const float*)d_in[2];
    const float* sinb     = (const float*)d_in[3];
    const float* q_pass   = (const float*)d_in[4];
    const float* q_rot    = (const float*)d_in[5];
    const float* k_pass   = (const float*)d_in[6];
    const float* k_rot    = (const float*)d_in[7];
    const float* kv_b     = (const float*)d_in[9];
    const float* wq_b     = (const float*)d_in[10];
    const float* wk       = (const float*)d_in[11];
    const float* k_norm   = (const float*)d_in[12];
    const float* wproj    = (const float*)d_in[13];
    const float* wproj_b  = (const float*)d_in[14];
    float* out = (float*)d_out;

    float *ql, *qbuf, *attn;
    cudaGetSymbolAddress((void**)&ql,   g_ql);
    cudaGetSymbolAddress((void**)&qbuf, g_q);
    cudaGetSymbolAddress((void**)&attn, g_attn);

    // one-time host-side resources (device work is identical every call)
    static cudaStream_t s2 = 0, s3 = 0;
    static cudaEvent_t  eF = 0, eD = 0, eQ = 0;
    if (!s2) {
        cudaStreamCreateWithFlags(&s2, cudaStreamNonBlocking);
        cudaStreamCreateWithFlags(&s3, cudaStreamNonBlocking);
        cudaEventCreateWithFlags(&eF, cudaEventDisableTiming);
        cudaEventCreateWithFlags(&eD, cudaEventDisableTiming);
        cudaEventCreateWithFlags(&eQ, cudaEventDisableTiming);
    }

    // fork side streams off the main (captured) stream
    cudaEventRecord(eF, 0);
    cudaStreamWaitEvent(s2, eF, 0);
    cudaStreamWaitEvent(s3, eF, 0);

    // main stream: ql (critical path)
    sgemm128_k<<<dim3(16, 16), 256>>>(q_latent, wq_b, ql,
        2048, 2048, 1536, 1536, 1536, 2048);
    // s2: ckv + wtmp (independent of ql)
    dual_k<<<dim3(3, 32), 256, 0, s2>>>(hs, wk, wproj);
    cudaEventRecord(eD, s2);
    // s3: q_abs (independent of everything until attn)
    tgemm_k<<<dim3(8, 32, 16), 256, 0, s3>>>(q_pass, kv_b, qbuf,
        2048, 512, 128, 128, 512, 9216,
        2048LL * 128, 256LL * 512, 576, 0);
    cudaEventRecord(eQ, s3);

    // main: prep needs ql + dual
    cudaStreamWaitEvent(0, eD, 0);
    prep_k<<<2048, 128>>>(cosb, sinb, k_pass, k_rot, q_rot, k_norm, wproj_b);
    // scores (triangular grid) + topk, overlapping q_abs on s3
    score_k<<<392, 256>>>();
    topk_k<<<1024, 1024>>>();
    // attn needs topk + q_abs + prep
    cudaStreamWaitEvent(0, eQ, 0);
    cudaFuncSetAttribute(attn_k, cudaFuncAttributeMaxDynamicSharedMemorySize, ATTN_SMEM);
    attn_k<<<2048, 256, ATTN_SMEM>>>();
    // final projection
    tgemm_k<<<dim3(2, 32, 16), 256>>>(attn, kv_b + 128 * 512, out,
        2048, 128, 512, 8192, 512, 2048,
        512, 256LL * 512, 128, 1);
}

// round 16
// speedup vs baseline: 1.0268x; 1.0156x over previous
#include <cuda_runtime.h>
#include <stdint.h>
#include <math.h>

#define SQ       2048
#define NH       16
#define DQK      576
#define KVL      512
#define NTOP     1024
#define SCALINGF 0.08838834764831845f  // 128^-0.5

// ------------------ device scratch (no allocation) ------------------
__device__ float g_ql  [SQ * 2048];
__device__ float g_ckv [SQ * 128];
__device__ float g_wtmp[SQ * NH];
__device__ float g_iq  [SQ * NH * 128];
__device__ float g_ik  [SQ * 128];
__device__ float g_w   [SQ * NH];
__device__ float g_q   [SQ * NH * DQK];
__device__ float g_kv  [SQ * DQK];          // tf32-pre-rounded (attention only)
__device__ float g_score[SQ * SQ];
__device__ int   g_topk [SQ * NTOP];
__device__ float g_attn [SQ * NH * KVL];

// ------------------ cp.async helpers ------------------
__device__ __forceinline__ void cp16(void* dst, const void* src) {
    unsigned s = (unsigned)__cvta_generic_to_shared(dst);
    asm volatile("cp.async.cg.shared.global [%0], [%1], 16;\n" :: "r"(s), "l"(src));
}
__device__ __forceinline__ void cp_commit() {
    asm volatile("cp.async.commit_group;\n" ::: "memory");
}
__device__ __forceinline__ void cp_wait1() {
    asm volatile("cp.async.wait_group 1;\n" ::: "memory");
}

// ------------------ tf32 mma helpers ------------------
__device__ __forceinline__ uint32_t cvt_tf32(float x) {
    uint32_t r; asm("cvt.rna.tf32.f32 %0, %1;" : "=r"(r) : "f"(x)); return r;
}
__device__ __forceinline__ void mma_tf32(float* c,
    uint32_t a0, uint32_t a1, uint32_t a2, uint32_t a3,
    uint32_t b0, uint32_t b1)
{
    asm volatile(
        "mma.sync.aligned.m16n8k8.row.col.f32.tf32.tf32.f32 "
        "{%0,%1,%2,%3}, {%4,%5,%6,%7}, {%8,%9}, {%0,%1,%2,%3};\n"
        : "+f"(c[0]), "+f"(c[1]), "+f"(c[2]), "+f"(c[3])
        : "r"(a0), "r"(a1), "r"(a2), "r"(a3), "r"(b0), "r"(b1));
}

// ------------------ fast exact-fp32 SGEMM: C = A @ B^T, 128x128 tiles ------------------
__global__ __launch_bounds__(256) void sgemm128_k(
    const float* __restrict__ A, const float* __restrict__ B, float* __restrict__ C,
    int M, int N, int K, int lda, int ldb, int ldc)
{
    __shared__ float As[16][132];
    __shared__ float Bs[16][132];
    int tid = threadIdx.x;
    int m0 = blockIdx.y * 128, n0 = blockIdx.x * 128;
    int row8 = (tid >> 4) << 3, col8 = (tid & 15) << 3;
    float acc[8][8] = {};

    for (int k0 = 0; k0 < K; k0 += 16) {
        #pragma unroll
        for (int u = 0; u < 2; u++) {
            int f = tid * 2 + u;
            int r = f >> 2, c = f & 3;
            float4 av = *(const float4*)&A[(long long)(m0 + r) * lda + k0 + c * 4];
            As[c * 4 + 0][r] = av.x; As[c * 4 + 1][r] = av.y;
            As[c * 4 + 2][r] = av.z; As[c * 4 + 3][r] = av.w;
            float4 bv = *(const float4*)&B[(long long)(n0 + r) * ldb + k0 + c * 4];
            Bs[c * 4 + 0][r] = bv.x; Bs[c * 4 + 1][r] = bv.y;
            Bs[c * 4 + 2][r] = bv.z; Bs[c * 4 + 3][r] = bv.w;
        }
        __syncthreads();
        #pragma unroll
        for (int kk = 0; kk < 16; kk++) {
            float a[8], b[8];
            *(float4*)&a[0] = *(float4*)&As[kk][row8];
            *(float4*)&a[4] = *(float4*)&As[kk][row8 + 4];
            *(float4*)&b[0] = *(float4*)&Bs[kk][col8];
            *(float4*)&b[4] = *(float4*)&Bs[kk][col8 + 4];
            #pragma unroll
            for (int i = 0; i < 8; i++)
                #pragma unroll
                for (int j = 0; j < 8; j++)
                    acc[i][j] = fmaf(a[i], b[j], acc[i][j]);
        }
        __syncthreads();
    }
    #pragma unroll
    for (int i = 0; i < 8; i++) {
        float4 v0 = { acc[i][0], acc[i][1], acc[i][2], acc[i][3] };
        float4 v1 = { acc[i][4], acc[i][5], acc[i][6], acc[i][7] };
        float* crow = &C[(long long)(m0 + row8 + i) * ldc + n0 + col8];
        *(float4*)&crow[0] = v0;
        *(float4*)&crow[4] = v1;
    }
}

// ------------------ dual exact-fp32 GEMM: ckv = hs@wk^T, wtmp = hs@wproj^T ------------------
__global__ __launch_bounds__(256) void dual_k(
    const float* __restrict__ hs, const float* __restrict__ wk,
    const float* __restrict__ wproj)
{
    __shared__ float As[16][65];
    __shared__ float Bs[16][65];
    int tid = threadIdx.x, tx = tid & 15, ty = tid >> 4;
    int m0 = blockIdx.y * 64, n0 = blockIdx.x * 64;
    float acc[4][4] = {};
    for (int k0 = 0; k0 < 2048; k0 += 16) {
        for (int e = tid; e < 1024; e += 256) {
            int m = e >> 4, k = e & 15;
            As[k][m] = hs[(long long)(m0 + m) * 2048 + k0 + k];
        }
        for (int e = tid; e < 1024; e += 256) {
            int n = e >> 4, k = e & 15;
            int gn = n0 + n;
            float v = 0.f;
            if (gn < 128)      v = wk[(long long)gn * 2048 + k0 + k];
            else if (gn < 144) v = wproj[(long long)(gn - 128) * 2048 + k0 + k];
            Bs[k][n] = v;
        }
        __syncthreads();
        #pragma unroll
        for (int kk = 0; kk < 16; kk++) {
            float a[4], b[4];
            #pragma unroll
            for (int i = 0; i < 4; i++) a[i] = As[kk][ty * 4 + i];
            #pragma unroll
            for (int j = 0; j < 4; j++) b[j] = Bs[kk][tx * 4 + j];
            #pragma unroll
            for (int i = 0; i < 4; i++)
                #pragma unroll
                for (int j = 0; j < 4; j++) acc[i][j] += a[i] * b[j];
        }
        __syncthreads();
    }
    #pragma unroll
    for (int i = 0; i < 4; i++) {
        int gm = m0 + ty * 4 + i;
        #pragma unroll
        for (int j = 0; j < 4; j++) {
            int gn = n0 + tx * 4 + j;
            if (gn < 128)      g_ckv[gm * 128 + gn] = acc[i][j];
            else if (gn < 144) g_wtmp[gm * 16 + gn - 128] = acc[i][j];
        }
    }
}

// ------------------ tensor-core GEMM, 3xTF32: C = A @ op(B) ------------------
__global__ __launch_bounds__(256) void tgemm_k(
    const float* __restrict__ A, const float* __restrict__ B, float* __restrict__ C,
    int M, int N, int K, int lda, int ldb, int ldc,
    long long sA, long long sB, long long sC, int transB)
{
    A += (long long)blockIdx.z * sA;
    B += (long long)blockIdx.z * sB;
    C += (long long)blockIdx.z * sC;
    __shared__ float As[64 * 33], Ae[64 * 33], Bs[64 * 33], Be[64 * 33];
    int tid = threadIdx.x, lane = tid & 31, warp = tid >> 5;
    int wm = (warp & 3) * 16, wn = (warp >> 2) * 32;
    int g = lane >> 2, tg = lane & 3;
    int m0 = blockIdx.y * 64, n0 = blockIdx.x * 64;
    float acc[4][4] = {};

    for (int k0 = 0; k0 < K; k0 += 32) {
        for (int e = tid; e < 2048; e += 256) {
            int m = e >> 5, k = e & 31;
            float v = A[(long long)(m0 + m) * lda + k0 + k];
            float t = __uint_as_float(cvt_tf32(v));
            As[m * 33 + k] = t;
            Ae[m * 33 + k] = __uint_as_float(cvt_tf32(v - t));
        }
        if (transB) {
            for (int e = tid; e < 2048; e += 256) {
                int n = e >> 5, k = e & 31;
                float v = B[(long long)(n0 + n) * ldb + k0 + k];
                float t = __uint_as_float(cvt_tf32(v));
                Bs[n * 33 + k] = t;
                Be[n * 33 + k] = __uint_as_float(cvt_tf32(v - t));
            }
        } else {
            for (int e = tid; e < 2048; e += 256) {
                int n = e & 63, k = e >> 6;
                float v = B[(long long)(k0 + k) * ldb + n0 + n];
                float t = __uint_as_float(cvt_tf32(v));
                Bs[n * 33 + k] = t;
                Be[n * 33 + k] = __uint_as_float(cvt_tf32(v - t));
            }
        }
        __syncthreads();
        #pragma unroll
        for (int kc = 0; kc < 4; kc++) {
            int kb = kc * 8;
            uint32_t a0 = __float_as_uint(As[(wm + g) * 33 + kb + tg]);
            uint32_t a1 = __float_as_uint(As[(wm + g + 8) * 33 + kb + tg]);
            uint32_t a2 = __float_as_uint(As[(wm + g) * 33 + kb + tg + 4]);
            uint32_t a3 = __float_as_uint(As[(wm + g + 8) * 33 + kb + tg + 4]);
            uint32_t r0 = __float_as_uint(Ae[(wm + g) * 33 + kb + tg]);
            uint32_t r1 = __float_as_uint(Ae[(wm + g + 8) * 33 + kb + tg]);
            uint32_t r2 = __float_as_uint(Ae[(wm + g) * 33 + kb + tg + 4]);
            uint32_t r3 = __float_as_uint(Ae[(wm + g + 8) * 33 + kb + tg + 4]);
            #pragma unroll
            for (int nc = 0; nc < 4; nc++) {
                uint32_t b0 = __float_as_uint(Bs[(wn + nc * 8 + g) * 33 + kb + tg]);
                uint32_t b1 = __float_as_uint(Bs[(wn + nc * 8 + g) * 33 + kb + tg + 4]);
                uint32_t e0 = __float_as_uint(Be[(wn + nc * 8 + g) * 33 + kb + tg]);
                uint32_t e1 = __float_as_uint(Be[(wn + nc * 8 + g) * 33 + kb + tg + 4]);
                mma_tf32(acc[nc], r0, r1, r2, r3, b0, b1);
                mma_tf32(acc[nc], a0, a1, a2, a3, e0, e1);
                mma_tf32(acc[nc], a0, a1, a2, a3, b0, b1);
            }
        }
        __syncthreads();
    }
    #pragma unroll
    for (int nc = 0; nc < 4; nc++) {
        int col = n0 + wn + nc * 8 + 2 * tg;
        float2 v0 = { acc[nc][0], acc[nc][1] };
        float2 v1 = { acc[nc][2], acc[nc][3] };
        *(float2*)&C[(long long)(m0 + wm + g) * ldc + col]     = v0;
        *(float2*)&C[(long long)(m0 + wm + g + 8) * ldc + col] = v1;
    }
}

// ------------------ prep: rope / rmsnorm / concats; kv tf32-pre-rounded ------------------
__global__ __launch_bounds__(128) void prep_k(
    const float* __restrict__ cosb, const float* __restrict__ sinb,
    const float* __restrict__ k_pass, const float* __restrict__ k_rot,
    const float* __restrict__ q_rot, const float* __restrict__ k_norm_w,
    const float* __restrict__ wproj_b)
{
    int s = blockIdx.x, t = threadIdx.x;
    const float* cs = cosb + s * 64;
    const float* sn = sinb + s * 64;
    if (t < 32) {
        float x0 = g_ckv[s * 128 + 2 * t], x1 = g_ckv[s * 128 + 2 * t + 1];
        g_ik[s * 128 + t]      = x0 * cs[t]      - x1 * sn[t];
        g_ik[s * 128 + 32 + t] = x1 * cs[32 + t] + x0 * sn[32 + t];
    }
    __shared__ float partials[4];
    float v = 0.f;
    if (t < 64) { float x = g_ckv[s * 128 + 64 + t]; v = x * x; }
    for (int o = 16; o > 0; o >>= 1) v += __shfl_xor_sync(0xffffffffu, v, o);
    if ((t & 31) == 0) partials[t >> 5] = v;
    __syncthreads();
    float var = (partials[0] + partials[1]) * (1.f / 64.f);
    float inv = rsqrtf(var + 1e-6f);
    if (t < 64)
        g_ik[s * 128 + 64 + t] = g_ckv[s * 128 + 64 + t] * inv * k_norm_w[t];
    for (int u = t; u < 16 * 32; u += 128) {
        int h = u >> 5, i = u & 31;
        float x0 = g_ql[s * 2048 + h * 128 + 2 * i];
        float x1 = g_ql[s * 2048 + h * 128 + 2 * i + 1];
        g_iq[(s * 16 + h) * 128 + i]      = x0 * cs[i]      - x1 * sn[i];
        g_iq[(s * 16 + h) * 128 + 32 + i] = x1 * cs[32 + i] + x0 * sn[32 + i];
    }
    for (int u = t; u < 16 * 64; u += 128) {
        int h = u >> 6, i = u & 63;
        g_iq[(s * 16 + h) * 128 + 64 + i] = g_ql[s * 2048 + h * 128 + 64 + i];
    }
    if (t < 16) g_w[s * 16 + t] = fabsf(g_wtmp[s * 16 + t] + wproj_b[t]);
    for (int u = t; u < 512; u += 128)
        g_kv[s * 576 + u] = __uint_as_float(cvt_tf32(k_pass[s * 512 + u]));
    if (t < 64)
        g_kv[s * 576 + 512 + t] = __uint_as_float(cvt_tf32(k_rot[s * 64 + t]));
    for (int u = t; u < 16 * 64; u += 128) {
        int h = u >> 6, j = u & 63;
        g_q[(s * 16 + h) * 576 + 512 + j] = q_rot[(h * 2048 + s) * 64 + j];
    }
}

// ------------------ indexer scores, triangular grid (fp32, exact) ------------------
__global__ __launch_bounds__(256) void score_k()
{
    __shared__ float Qs[32][65];
    __shared__ float Ks[32][65];
    __shared__ float ws[64];
    int bid = blockIdx.x;
    int i = 0, c = 0;
    #pragma unroll
    for (int r = 0; r < 16; r++) {
        int n = 17 + r;
        if (bid >= c && bid < c + n) { i = r; break; }
        c += n;
    }
    int q0 = 1024 + i * 64;
    int k0 = (bid - c) * 64;
    int tid = threadIdx.x, tx = tid & 15, ty = tid >> 4;
    float acc[4][4] = {};
    for (int h = 0; h < 16; h++) {
        float dacc[4][4] = {};
        for (int d0 = 0; d0 < 128; d0 += 32) {
            __syncthreads();
            for (int e = tid; e < 2048; e += 256) {
                int m = e >> 5, dd = e & 31;
                Qs[dd][m] = g_iq[((q0 + m) * 16 + h) * 128 + d0 + dd];
                Ks[dd][m] = g_ik[(k0 + m) * 128 + d0 + dd];
            }
            __syncthreads();
            #pragma unroll
            for (int dd = 0; dd < 32; dd++) {
                float a[4], b[4];
                #pragma unroll
                for (int i2 = 0; i2 < 4; i2++) a[i2] = Qs[dd][ty * 4 + i2];
                #pragma unroll
                for (int j = 0; j < 4; j++) b[j] = Ks[dd][tx * 4 + j];
                #pragma unroll
                for (int i2 = 0; i2 < 4; i2++)
                    #pragma unroll
                    for (int j = 0; j < 4; j++) dacc[i2][j] += a[i2] * b[j];
            }
        }
        __syncthreads();
        if (tid < 64) ws[tid] = g_w[(q0 + tid) * 16 + h];
        __syncthreads();
        #pragma unroll
        for (int i2 = 0; i2 < 4; i2++)
            #pragma unroll
            for (int j = 0; j < 4; j++)
                acc[i2][j] += ws[ty * 4 + i2] * fmaxf(dacc[i2][j] * SCALINGF, 0.f);
    }
    #pragma unroll
    for (int i2 = 0; i2 < 4; i2++)
        #pragma unroll
        for (int j = 0; j < 4; j++)
            g_score[(q0 + ty * 4 + i2) * 2048 + k0 + tx * 4 + j] = acc[i2][j];
}

// ------------------ top-1024 per row (bitonic, jax tie-break) ------------------
__global__ __launch_bounds__(1024) void topk_k()
{
    __shared__ unsigned long long key[2048];
    int q = 1024 + blockIdx.x;
    int t = threadIdx.x;
    for (int u = t; u < 2048; u += 1024) {
        unsigned long long kk = 0ull;
        if (u <= q) {
            unsigned int b = __float_as_uint(g_score[q * 2048 + u]);  // score >= 0
            kk = ((unsigned long long)b << 32) | (unsigned int)(~u);
        }
        key[u] = kk;
    }
    __syncthreads();
    for (int ks = 2; ks <= 2048; ks <<= 1) {
        for (int j = ks >> 1; j > 0; j >>= 1) {
            int i = ((t & ~(j - 1)) << 1) | (t & (j - 1));
            int p = i | j;
            bool desc = (i & ks) == 0;
            unsigned long long a = key[i], b = key[p];
            if ((a < b) == desc) { key[i] = b; key[p] = a; }
            __syncthreads();
        }
    }
    g_topk[q * 1024 + t] = (int)(~(unsigned int)(key[t] & 0xFFFFFFFFull));
}

// ------------------ flash attention: 256 thr, 16-key tiles, 2 blocks/SM ------------------
#define KP   580
#define PPP  20
#define KVB16 (16 * KP)
#define ATTN_SMEM ((2*KVB16 + 8*272 + 16*PPP + 32 + 1024) * 4)

__global__ __launch_bounds__(256, 2) void attn_k(int qbase)
{
    extern __shared__ float sm[];
    float* kvb  = sm;
    float* part = kvb + 2 * KVB16;
    float* p_s  = part + 8 * 272;
    float* f_s  = p_s + 16 * PPP;
    float* l_s  = f_s + 16;
    int*   sel_s = (int*)(l_s + 16);

    int q = qbase + blockIdx.x, t = threadIdx.x;
    int L = (q < 1024) ? (q + 1) : 1024;
    const int* sel = (q < 1024) ? (const int*)0 : &g_topk[q * 1024];
    int nt = (L + 15) >> 4;

    int wid = t >> 5, lane = t & 31;
    int g = lane >> 2, tg = lane & 3;
    int gj = t >> 4, gf = t & 15;

    {
        float* dst = kvb + gj * KP;
        if (gj < L) {
            int keyi = sel ? sel[gj] : gj;
            const float* src = &g_kv[keyi * 576];
            #pragma unroll
            for (int i = 0; i < 9; i++) {
                int f4 = gf + 16 * i;
                cp16(dst + f4 * 4, src + f4 * 4);
            }
        } else {
            float4 z = {0, 0, 0, 0};
            #pragma unroll
            for (int i = 0; i < 9; i++)
                *(float4*)(dst + (gf + 16 * i) * 4) = z;
        }
    }
    cp_commit();

    if (sel)
        for (int i = t; i < 1024; i += 256) sel_s[i] = sel[i];

    uint32_t qr[9][4];
    {
        const float* qrow = &g_q[q * 16 * 576];
        #pragma unroll
        for (int i = 0; i < 9; i++) {
            int kb = (wid + 8 * i) * 8;
            qr[i][0] = cvt_tf32(qrow[g * 576 + kb + tg]);
            qr[i][1] = cvt_tf32(qrow[(g + 8) * 576 + kb + tg]);
            qr[i][2] = cvt_tf32(qrow[g * 576 + kb + tg + 4]);
            qr[i][3] = cvt_tf32(qrow[(g + 8) * 576 + kb + tg + 4]);
        }
    }
    __syncthreads();

    int sh = 2 * wid + (lane >> 4);
    int sk = lane & 15;
    float m_cur = -1e30f, l_cur = 0.f;
    float acc[8][4] = {};

    for (int tile = 0; tile < nt; tile++) {
        int buf = tile & 1;
        float* kvs = kvb + buf * KVB16;
        if (tile + 1 < nt) {
            int jj = (tile + 1) * 16 + gj;
            float* dst = kvb + (buf ^ 1) * KVB16 + gj * KP;
            if (jj < L) {
                int keyi = sel ? sel_s[jj] : jj;
                const float* src = &g_kv[keyi * 576];
                #pragma unroll
                for (int i = 0; i < 9; i++) {
                    int f4 = gf + 16 * i;
                    cp16(dst + f4 * 4, src + f4 * 4);
                }
            } else {
                float4 z = {0, 0, 0, 0};
                #pragma unroll
                for (int i = 0; i < 9; i++)
                    *(float4*)(dst + (gf + 16 * i) * 4) = z;
            }
        }
        cp_commit();
        cp_wait1();
        __syncthreads();

        {
            float c4[2][4] = {};
            #pragma unroll
            for (int i = 0; i < 9; i++) {
                int kb = (wid + 8 * i) * 8;
                #pragma unroll
                for (int nc2 = 0; nc2 < 2; nc2++) {
                    uint32_t b0 = __float_as_uint(kvs[(nc2 * 8 + g) * KP + kb + tg]);
                    uint32_t b1 = __float_as_uint(kvs[(nc2 * 8 + g) * KP + kb + tg + 4]);
                    mma_tf32(c4[nc2], qr[i][0], qr[i][1], qr[i][2], qr[i][3], b0, b1);
                }
            }
            float* pp = part + wid * 272;
            #pragma unroll
            for (int nc2 = 0; nc2 < 2; nc2++) {
                pp[g * 17 + nc2 * 8 + 2 * tg]           = c4[nc2][0];
                pp[g * 17 + nc2 * 8 + 2 * tg + 1]       = c4[nc2][1];
                pp[(g + 8) * 17 + nc2 * 8 + 2 * tg]     = c4[nc2][2];
                pp[(g + 8) * 17 + nc2 * 8 + 2 * tg + 1] = c4[nc2][3];
            }
        }
        __syncthreads();

        {
            float val = 0.f;
            #pragma unroll
            for (int ws = 0; ws < 8; ws++)
                val += part[ws * 272 + sh * 17 + sk];
            val *= SCALINGF;
            int jj = tile * 16 + sk;
            val = (jj < L) ? val : -1e30f;
            float mx = val;
            #pragma unroll
            for (int o = 8; o > 0; o >>= 1)
                mx = fmaxf(mx, __shfl_xor_sync(0xffffffffu, mx, o));
            float m_new = fmaxf(m_cur, mx);
            float factor = __expf(m_cur - m_new);
            float p = __uint_as_float(cvt_tf32(__expf(val - m_new)));
            float ps = p;
            #pragma unroll
            for (int o = 8; o > 0; o >>= 1)
                ps += __shfl_xor_sync(0xffffffffu, ps, o);
            l_cur = l_cur * factor + ps;
            m_cur = m_new;
            p_s[sh * PPP + sk] = p;
            if (sk == 0) f_s[sh] = factor;
        }
        __syncthreads();

        {
            int nb = wid * 64;
            float fg = f_s[g], fg8 = f_s[g + 8];
            #pragma unroll
            for (int c2 = 0; c2 < 8; c2++) {
                acc[c2][0] *= fg;  acc[c2][1] *= fg;
                acc[c2][2] *= fg8; acc[c2][3] *= fg8;
            }
            #pragma unroll
            for (int kc = 0; kc < 2; kc++) {
                uint32_t a0 = __float_as_uint(p_s[g * PPP + kc * 8 + tg]);
                uint32_t a1 = __float_as_uint(p_s[(g + 8) * PPP + kc * 8 + tg]);
                uint32_t a2 = __float_as_uint(p_s[g * PPP + kc * 8 + tg + 4]);
                uint32_t a3 = __float_as_uint(p_s[(g + 8) * PPP + kc * 8 + tg + 4]);
                #pragma unroll
                for (int c2 = 0; c2 < 8; c2++) {
                    uint32_t b0 = __float_as_uint(kvs[(kc * 8 + tg) * KP + nb + c2 * 8 + g]);
                    uint32_t b1 = __float_as_uint(kvs[(kc * 8 + tg + 4) * KP + nb + c2 * 8 + g]);
                    mma_tf32(acc[c2], a0, a1, a2, a3, b0, b1);
                }
            }
        }
        __syncthreads();
    }

    if (sk == 0) l_s[sh] = l_cur;
    __syncthreads();

    {
        int nb = wid * 64;
        float ig = 1.f / l_s[g], ig8 = 1.f / l_s[g + 8];
        #pragma unroll
        for (int c2 = 0; c2 < 8; c2++) {
            int d = nb + c2 * 8 + 2 * tg;
            float2 v0 = { acc[c2][0] * ig,  acc[c2][1] * ig  };
            float2 v1 = { acc[c2][2] * ig8, acc[c2][3] * ig8 };
            *(float2*)&g_attn[(q * 16 + g) * 512 + d]       = v0;
            *(float2*)&g_attn[(q * 16 + g + 8) * 512 + d]   = v1;
        }
    }
}

// ------------------ launcher: fork-join streams for DAG overlap ------------------
extern "C" void kernel_launch(void* const* d_in, const int* in_sizes, int n_in,
                              void* d_out, int out_size)
{
    const float* q_latent = (const float*)d_in[0];
    const float* hs       = (const float*)d_in[1];
    const float* cosb     = (const float*)d_in[2];
    const float* sinb     = (const float*)d_in[3];
    const float* q_pass   = (const float*)d_in[4];
    const float* q_rot    = (const float*)d_in[5];
    const float* k_pass   = (const float*)d_in[6];
    const float* k_rot    = (const float*)d_in[7];
    const float* kv_b     = (const float*)d_in[9];
    const float* wq_b     = (const float*)d_in[10];
    const float* wk       = (const float*)d_in[11];
    const float* k_norm   = (const float*)d_in[12];
    const float* wproj    = (const float*)d_in[13];
    const float* wproj_b  = (const float*)d_in[14];
    float* out = (float*)d_out;

    float *ql, *qbuf, *attn;
    cudaGetSymbolAddress((void**)&ql,   g_ql);
    cudaGetSymbolAddress((void**)&qbuf, g_q);
    cudaGetSymbolAddress((void**)&attn, g_attn);

    // one-time host-side resources (device work is identical every call)
    static cudaStream_t s2 = 0, s3 = 0;
    static cudaEvent_t  eF = 0, eD = 0, eQ = 0, eP = 0, eA = 0;
    if (!s2) {
        cudaStreamCreateWithFlags(&s2, cudaStreamNonBlocking);
        cudaStreamCreateWithFlags(&s3, cudaStreamNonBlocking);
        cudaEventCreateWithFlags(&eF, cudaEventDisableTiming);
        cudaEventCreateWithFlags(&eD, cudaEventDisableTiming);
        cudaEventCreateWithFlags(&eQ, cudaEventDisableTiming);
        cudaEventCreateWithFlags(&eP, cudaEventDisableTiming);
        cudaEventCreateWithFlags(&eA, cudaEventDisableTiming);
        cudaFuncSetAttribute(attn_k, cudaFuncAttributeMaxDynamicSharedMemorySize, ATTN_SMEM);
    }

    // fork side streams
    cudaEventRecord(eF, 0);
    cudaStreamWaitEvent(s2, eF, 0);
    cudaStreamWaitEvent(s3, eF, 0);

    // main: ql (critical path for score)
    sgemm128_k<<<dim3(16, 16), 256>>>(q_latent, wq_b, ql,
        2048, 2048, 1536, 1536, 1536, 2048);
    // s2: ckv + wtmp
    dual_k<<<dim3(3, 32), 256, 0, s2>>>(hs, wk, wproj);
    cudaEventRecord(eD, s2);
    // s3: q_abs
    tgemm_k<<<dim3(8, 32, 16), 256, 0, s3>>>(q_pass, kv_b, qbuf,
        2048, 512, 128, 128, 512, 9216,
        2048LL * 128, 256LL * 512, 576, 0);
    cudaEventRecord(eQ, s3);

    // main: prep needs ql + dual
    cudaStreamWaitEvent(0, eD, 0);
    prep_k<<<2048, 128>>>(cosb, sinb, k_pass, k_rot, q_rot, k_norm, wproj_b);
    cudaEventRecord(eP, 0);

    // s3: low-half attention (q < 1024, no topk needed) — overlaps score+topk
    cudaStreamWaitEvent(s3, eP, 0);   // s3 already ordered after q_abs
    attn_k<<<1024, 256, ATTN_SMEM, s3>>>(0);
    cudaEventRecord(eA, s3);

    // main: scores (triangular) + topk
    score_k<<<392, 256>>>();
    topk_k<<<1024, 1024>>>();

    // main: high-half attention (needs topk + q_abs via eA's stream order? no — needs eQ too)
    cudaStreamWaitEvent(0, eQ, 0);
    attn_k<<<1024, 256, ATTN_SMEM>>>(1024);
    // join low-half before final projection (reads all of g_attn)
    cudaStreamWaitEvent(0, eA, 0);
    tgemm_k<<<dim3(2, 32, 16), 256>>>(attn, kv_b + 128 * 512, out,
        2048, 128, 512, 8192, 512, 2048,
        512, 256LL * 512, 128, 1);
}